// round 12
// baseline (speedup 1.0000x reference)
#include <cuda_runtime.h>
#include <math.h>

#define Bn 4
#define CNn 16
#define NAn 16
#define CSn 32
#define JUn 512

// dynamic-smem word offsets for k_routeT (total 16644 words ~= 66.6KB)
#define AOFF 0        // sA: [2][1280] u32 (s-GEMM A, 64m x 20, double buf)
#define BOFF 2560     // sB: [2][2176] u32 (s-GEMM B / T-phase Ut 16m x 136)
#define COFF 6912     // c_smf[512]
#define FOFF 7424     // fb[512]
#define SCOFF 7936    // scp[1] (+pad)
#define VOFF 7940     // vt: [64][136] u32 (v tile, tf32)
#define SMEM_WORDS 16644
#define SMEM_BYTES (SMEM_WORDS*4)

// -------- scratch (device globals; no allocations anywhere) --------
__device__ float    g_msqp[Bn*4*16];       // squash-norm partials (b, gl, 16)
__device__ float    g_WgT[128*512];        // fp32 Wg permuted: [ik=k*32+i][col'=u*16+j]
__device__ unsigned g_Ut[Bn*1024*128];     // tf32 UNSCALED U (flat reinterpret view)
__device__ float    g_apart[Bn*16*4*512];  // agreement partials [b][mblk][cblk][i*16+j]
__device__ float    g_blog[Bn*512];        // routing logits
__device__ float    g_gpart[Bn*16*512];    // colsum partials of final v [b][mblk][col']
__device__ float    g_va[Bn*NAn*CSn];      // aspect output

// ---------------- helpers ----------------
__device__ __forceinline__ unsigned f2tf(float f){
    unsigned r; asm("cvt.rna.tf32.f32 %0, %1;" : "=r"(r) : "f"(f)); return r;
}
__device__ __forceinline__ void mma_tf32(float* d, unsigned a0, unsigned a1,
                                         unsigned a2, unsigned a3,
                                         unsigned b0, unsigned b1){
    asm volatile(
        "mma.sync.aligned.m16n8k8.row.col.f32.tf32.tf32.f32 "
        "{%0,%1,%2,%3}, {%4,%5,%6,%7}, {%8,%9}, {%0,%1,%2,%3};"
        : "+f"(d[0]), "+f"(d[1]), "+f"(d[2]), "+f"(d[3])
        : "r"(a0), "r"(a1), "r"(a2), "r"(a3), "r"(b0), "r"(b1));
}
__device__ __forceinline__ unsigned s2u(const void* p){
    return (unsigned)__cvta_generic_to_shared(p);
}
__device__ __forceinline__ void cpa16(unsigned d, const void* s){
    asm volatile("cp.async.cg.shared.global [%0], [%1], 16;" :: "r"(d), "l"(s));
}
__device__ __forceinline__ void cpa_commit(){ asm volatile("cp.async.commit_group;"); }
template<int N> __device__ __forceinline__ void cpa_wait(){
    asm volatile("cp.async.wait_group %0;" :: "n"(N));
}

// ---------------- primary: Wg permute + 64m x 64n GEMM (inline cvt), k=512 ----------------
// grid (16 nblk, 2 mblk, 4 b)
__global__ __launch_bounds__(256) void k_primary(const float* __restrict__ Wg,
                                                 const float* __restrict__ Wp,
                                                 const float* __restrict__ X,
                                                 const float* __restrict__ bp){
    __shared__ __align__(16) unsigned sA[2][1280];  // [64m][20]
    __shared__ __align__(16) unsigned sB[2][1152];  // [16k][72]
    __shared__ float red[8];
    int nblk = blockIdx.x, mblk = blockIdx.y, b = blockIdx.z;
    int n0 = nblk*64, m0 = mblk*64;
    int tid = threadIdx.x, w = tid>>5, lane = tid&31, gid = lane>>2, t4 = lane&3;
    int wm = w>>1, wn = w&1;

    // Wg permute: 512 elems per block (128 blocks cover 65536)
    {
        int lb = blockIdx.x + blockIdx.y*16 + blockIdx.z*32;
        #pragma unroll
        for (int r = 0; r < 2; r++){
            int e = lb*512 + r*256 + tid;
            int ik = e >> 9, col = e & 511;
            int uu = col >> 4, j = col & 15, i = ik & 31, k = ik >> 5;
            g_WgT[e] = Wg[((i*16 + j)*32 + uu)*4 + k];
        }
    }

    const float* Ap = Wp + (size_t)m0*512;
    const float* Bp = X + (size_t)b*524288;
    int arow = tid>>2, aq = tid&3;
    int brow = tid>>4, bq = tid&15;
    float4 ra = *(const float4*)(Ap + (size_t)arow*512 + aq*4);
    float4 rb = *(const float4*)(Bp + (size_t)brow*1024 + n0 + bq*4);
    float d[4][4] = {};
    for (int ch = 0; ch < 32; ch++){
        int buf = ch & 1;
        {
            uint4 oa; oa.x=f2tf(ra.x); oa.y=f2tf(ra.y); oa.z=f2tf(ra.z); oa.w=f2tf(ra.w);
            *(uint4*)&sA[buf][arow*20 + aq*4] = oa;
            uint4 ob; ob.x=f2tf(rb.x); ob.y=f2tf(rb.y); ob.z=f2tf(rb.z); ob.w=f2tf(rb.w);
            *(uint4*)&sB[buf][brow*72 + bq*4] = ob;
        }
        if (ch < 31){
            ra = *(const float4*)(Ap + (size_t)arow*512 + (ch+1)*16 + aq*4);
            rb = *(const float4*)(Bp + (size_t)((ch+1)*16+brow)*1024 + n0 + bq*4);
        }
        __syncthreads();
        #pragma unroll
        for (int ks = 0; ks < 2; ks++){
            int rbse = (wm*16+gid)*20 + ks*8 + t4;
            unsigned a0 = sA[buf][rbse], a1 = sA[buf][rbse+160];
            unsigned a2 = sA[buf][rbse+4], a3 = sA[buf][rbse+164];
            #pragma unroll
            for (int nt = 0; nt < 4; nt++){
                int cb = (ks*8+t4)*72 + wn*32 + nt*8 + gid;
                unsigned b0 = sB[buf][cb], b1 = sB[buf][cb + 288];
                mma_tf32(d[nt], a0, a1, a2, a3, b0, b1);
            }
        }
        __syncthreads();
    }
    float ssq = 0.f;
    unsigned* Ub = g_Ut + (size_t)b*131072;
    int mA = m0 + wm*16 + gid, mB = mA + 8;
    float biasA = bp[mA], biasB = bp[mB];
    #pragma unroll
    for (int nt = 0; nt < 4; nt++){
        int col = n0 + wn*32 + nt*8 + t4*2;
        float v0 = d[nt][0]+biasA, v1 = d[nt][1]+biasA;
        float v2 = d[nt][2]+biasB, v3 = d[nt][3]+biasB;
        uint2 pa; pa.x = f2tf(v0); pa.y = f2tf(v1);
        uint2 pb; pb.x = f2tf(v2); pb.y = f2tf(v3);
        *(uint2*)&Ub[(size_t)mA*1024 + col] = pa;
        *(uint2*)&Ub[(size_t)mB*1024 + col] = pb;
        ssq += v0*v0+v1*v1+v2*v2+v3*v3;
    }
    #pragma unroll
    for (int o = 16; o; o >>= 1) ssq += __shfl_xor_sync(0xffffffffu, ssq, o);
    if (lane == 0) red[w] = ssq;
    __syncthreads();
    if (tid < 2){
        float s = red[tid*4] + red[tid*4+1] + red[tid*4+2] + red[tid*4+3];
        g_msqp[(b*4 + mblk*2 + tid)*16 + nblk] = s;
    }
}

// ---------------- fused route(+T): 64m x 128col' s-GEMM, squash, in-block T-GEMM + agreement ----------------
// grid (4 cblk, 16 mblk, 4 b); dynamic smem SMEM_BYTES; 2 blocks/SM
__global__ __launch_bounds__(256, 2) void k_routeT(int t){
    extern __shared__ __align__(16) float sp[];
    unsigned* sA = (unsigned*)sp + AOFF;     // [2][1280]
    unsigned* sB = (unsigned*)sp + BOFF;     // [2][2176]
    float* c_smf = sp + COFF;
    float* fb    = sp + FOFF;
    float* scp1  = sp + SCOFF;
    unsigned* vt = (unsigned*)sp + VOFF;     // [64][136]
    int cblk = blockIdx.x, mblk = blockIdx.y, b = blockIdx.z;
    int m0 = mblk*64, c0 = cblk*128;
    int tid = threadIdx.x, w = tid>>5, lane = tid&31, gid = lane>>2, t4 = lane&3;
    int wm = w>>2, wn = w&3;

    if (tid == 0){
        int grp = mblk >> 2;
        float s = 0.f;
        #pragma unroll
        for (int p = 0; p < 16; p++) s += g_msqp[(b*4+grp)*16 + p];
        scp1[0] = sqrtf(s)/(1.f+s);
    }
    if (t >= 1){
        #pragma unroll
        for (int r = 0; r < 2; r++){
            int e = r*256 + tid;
            float s = (t == 2) ? g_blog[b*512 + e] : 0.f;
            const float* ap = g_apart + (size_t)b*32768 + e;
            #pragma unroll
            for (int p = 0; p < 64; p++) s += ap[p*512];
            fb[e] = s;
        }
    } else {
        c_smf[tid] = 0.0625f; c_smf[tid+256] = 0.0625f;
    }
    __syncthreads();
    if (t == 1 && mblk == 0 && cblk == 0)
        for (int e = tid; e < 512; e += 256) g_blog[b*512 + e] = fb[e];
    if (t >= 1 && tid < 32){
        int i = tid;
        float row[CNn], mx = -1e30f;
        #pragma unroll
        for (int j = 0; j < CNn; j++){ row[j] = fb[i*16 + j]; mx = fmaxf(mx, row[j]); }
        float sum = 0.f;
        #pragma unroll
        for (int j = 0; j < CNn; j++){ row[j] = expf(row[j]-mx); sum += row[j]; }
        float inv = 1.f/sum;
        #pragma unroll
        for (int j = 0; j < CNn; j++) c_smf[i*16 + j] = row[j]*inv;
    }
    __syncthreads();
    float sc = scp1[0];

    const unsigned* Ag = g_Ut + (size_t)b*131072 + (size_t)m0*128;
    int brow = tid >> 4;
    int bcol4 = (tid & 15)*2;
    const float4* c4p0 = (const float4*)&c_smf[0];

#define RT_STAGE_A(ch, bf) { \
    int row = tid>>2, q = tid&3; \
    cpa16(s2u(&sA[(bf)*1280 + row*20 + q*4]), Ag + row*128 + (ch)*16 + q*4); \
    cpa_commit(); }

    float4 curB0, curB1;
    {
        const float4* src = (const float4*)(g_WgT + (size_t)brow*512 + c0) + bcol4;
        curB0 = src[0]; curB1 = src[1];
    }
    RT_STAGE_A(0, 0);
    float d[2][4][4] = {};
    for (int ch = 0; ch < 8; ch++){
        int buf = ch & 1;
        if (ch < 7) RT_STAGE_A(ch+1, buf^1);
        {
            int i = ((ch & 1)*16 + brow);
            float4 cv0 = c4p0[i*4 + (bcol4 & 3)];
            float4 cv1 = c4p0[i*4 + ((bcol4+1) & 3)];
            uint4 o0, o1;
            o0.x=f2tf(curB0.x*cv0.x); o0.y=f2tf(curB0.y*cv0.y);
            o0.z=f2tf(curB0.z*cv0.z); o0.w=f2tf(curB0.w*cv0.w);
            o1.x=f2tf(curB1.x*cv1.x); o1.y=f2tf(curB1.y*cv1.y);
            o1.z=f2tf(curB1.z*cv1.z); o1.w=f2tf(curB1.w*cv1.w);
            uint4* dst = (uint4*)&sB[buf*2176 + brow*136 + bcol4*4];
            dst[0] = o0; dst[1] = o1;
        }
        if (ch < 7){
            const float4* src = (const float4*)(g_WgT + (size_t)((ch+1)*16+brow)*512 + c0) + bcol4;
            curB0 = src[0]; curB1 = src[1];
        }
        if (ch < 7) cpa_wait<1>(); else cpa_wait<0>();
        __syncthreads();
        #pragma unroll
        for (int ks = 0; ks < 2; ks++){
            unsigned a[2][4];
            #pragma unroll
            for (int mt = 0; mt < 2; mt++){
                int rb = buf*1280 + (wm*32 + mt*16 + gid)*20 + ks*8 + t4;
                a[mt][0]=sA[rb]; a[mt][1]=sA[rb+160];
                a[mt][2]=sA[rb+4]; a[mt][3]=sA[rb+164];
            }
            #pragma unroll
            for (int nt = 0; nt < 4; nt++){
                int cb = buf*2176 + (ks*8+t4)*136 + wn*32 + nt*8 + gid;
                unsigned b0 = sB[cb], b1 = sB[cb + 544];
                #pragma unroll
                for (int mt = 0; mt < 2; mt++)
                    mma_tf32(d[mt][nt], a[mt][0],a[mt][1],a[mt][2],a[mt][3], b0, b1);
            }
        }
        __syncthreads();
    }

    // squash over j (sc applied here; Ut unscaled)
    #pragma unroll
    for (int mt = 0; mt < 2; mt++){
        #pragma unroll
        for (int off = 0; off < 2; off++){
            float p0 = d[mt][0][off*2]*d[mt][0][off*2] + d[mt][0][off*2+1]*d[mt][0][off*2+1]
                     + d[mt][1][off*2]*d[mt][1][off*2] + d[mt][1][off*2+1]*d[mt][1][off*2+1];
            float p1 = d[mt][2][off*2]*d[mt][2][off*2] + d[mt][2][off*2+1]*d[mt][2][off*2+1]
                     + d[mt][3][off*2]*d[mt][3][off*2] + d[mt][3][off*2+1]*d[mt][3][off*2+1];
            p0 += __shfl_xor_sync(0xffffffffu, p0, 1); p0 += __shfl_xor_sync(0xffffffffu, p0, 2);
            p1 += __shfl_xor_sync(0xffffffffu, p1, 1); p1 += __shfl_xor_sync(0xffffffffu, p1, 2);
            float q0 = sc*sc*p0, q1 = sc*sc*p1;
            float f0 = sc*sqrtf(q0)/(1.f + q0), f1 = sc*sqrtf(q1)/(1.f + q1);
            d[mt][0][off*2] *= f0; d[mt][0][off*2+1] *= f0;
            d[mt][1][off*2] *= f0; d[mt][1][off*2+1] *= f0;
            d[mt][2][off*2] *= f1; d[mt][2][off*2+1] *= f1;
            d[mt][3][off*2] *= f1; d[mt][3][off*2+1] *= f1;
        }
    }
    if (t < 2){
        // ---- write v tile to smem (tf32), then in-block T-GEMM + agreement ----
        #pragma unroll
        for (int mt = 0; mt < 2; mt++)
            #pragma unroll
            for (int off = 0; off < 2; off++){
                int m = wm*32 + mt*16 + gid + off*8;     // local 0..63
                #pragma unroll
                for (int nt = 0; nt < 4; nt++){
                    int col = wn*32 + nt*8 + t4*2;       // local 0..127
                    vt[m*136 + col]     = f2tf(d[mt][nt][off*2]);
                    vt[m*136 + col + 1] = f2tf(d[mt][nt][off*2+1]);
                }
            }
        __syncthreads();
        // T-GEMM: T[128ik][128ju] = sum_{m in block} Ut[m][ik] * v[m][ju]
        int wik = w >> 1, wju = w & 1;
        float d2[2][8][4] = {};
#define T_STAGE(ch, bf) { \
    { int f=tid;     int row=f>>5,q=f&31; cpa16(s2u(&sB[(bf)*2176+row*136+q*4]), Ag + (size_t)((ch)*16+row)*128 + q*4); } \
    { int f=tid+256; int row=f>>5,q=f&31; cpa16(s2u(&sB[(bf)*2176+row*136+q*4]), Ag + (size_t)((ch)*16+row)*128 + q*4); } \
    cpa_commit(); }
        T_STAGE(0, 0);
        for (int ch = 0; ch < 4; ch++){
            int buf = ch & 1;
            if (ch < 3){ T_STAGE(ch+1, buf^1); cpa_wait<1>(); } else cpa_wait<0>();
            __syncthreads();
            #pragma unroll
            for (int ks = 0; ks < 2; ks++){
                unsigned a[2][4];
                #pragma unroll
                for (int mt = 0; mt < 2; mt++){
                    int ikb = wik*32 + mt*16 + gid;
                    a[mt][0] = sB[buf*2176 + (ks*8+t4)*136 + ikb];
                    a[mt][1] = sB[buf*2176 + (ks*8+t4)*136 + ikb + 8];
                    a[mt][2] = sB[buf*2176 + (ks*8+t4+4)*136 + ikb];
                    a[mt][3] = sB[buf*2176 + (ks*8+t4+4)*136 + ikb + 8];
                }
                #pragma unroll
                for (int nt = 0; nt < 8; nt++){
                    int cb = wju*64 + nt*8 + gid;
                    unsigned b0 = vt[(ch*16 + ks*8+t4)*136 + cb];
                    unsigned b1 = vt[(ch*16 + ks*8+t4+4)*136 + cb];
                    mma_tf32(d2[0][nt], a[0][0],a[0][1],a[0][2],a[0][3], b0, b1);
                    mma_tf32(d2[1][nt], a[1][0],a[1][1],a[1][2],a[1][3], b0, b1);
                }
            }
            __syncthreads();
        }
        // agreement: dot T tile with WgT, accumulate per (i,j)
        float p[4][4] = {};
        #pragma unroll
        for (int mt = 0; mt < 2; mt++)
            #pragma unroll
            for (int off = 0; off < 2; off++){
                int r = wik*32 + mt*16 + off*8 + gid;
                #pragma unroll
                for (int nt = 0; nt < 8; nt++){
                    int col = c0 + wju*64 + nt*8 + t4*2;
                    float2 wv = *(const float2*)&g_WgT[(size_t)r*512 + col];
                    int pi = mt*2 + off, js = (nt & 1)*2;
                    p[pi][js]   += d2[mt][nt][off*2]   * wv.x;
                    p[pi][js+1] += d2[mt][nt][off*2+1] * wv.y;
                }
            }
        float* sag = sp + AOFF;   // alias sA+sB region [4096 words]; mma reads done
        #pragma unroll
        for (int pi = 0; pi < 4; pi++)
            #pragma unroll
            for (int js = 0; js < 4; js++)
                sag[(w*32 + lane)*16 + pi*4 + js] = p[pi][js];
        __syncthreads();
        float wsc = sc*(1.f/1024.f);
        #pragma unroll
        for (int it = 0; it < 2; it++){
            int idx = it*256 + tid;
            int i = idx >> 4, j = idx & 15;
            int lgid = i & 7, pi = ((i>>4)<<1) | ((i>>3)&1);
            int lt4 = (j & 7) >> 1, js = ((j>>3)<<1) | (j&1);
            int ln = lgid*4 + lt4;
            float s = 0.f;
            #pragma unroll
            for (int ww = 0; ww < 8; ww++) s += sag[(ww*32 + ln)*16 + pi*4 + js];
            g_apart[(((size_t)b*16 + mblk)*4 + cblk)*512 + idx] = s*wsc;
        }
    } else {
        float* cs_sm = c_smf;   // reuse (c no longer needed)
        #pragma unroll
        for (int nt = 0; nt < 4; nt++)
            #pragma unroll
            for (int c = 0; c < 2; c++){
                float s = 0.f;
                #pragma unroll
                for (int mt = 0; mt < 2; mt++) s += d[mt][nt][c] + d[mt][nt][2+c];
                s += __shfl_xor_sync(0xffffffffu, s, 4);
                s += __shfl_xor_sync(0xffffffffu, s, 8);
                s += __shfl_xor_sync(0xffffffffu, s, 16);
                if (gid == 0) cs_sm[wm*128 + wn*32 + nt*8 + t4*2 + c] = s;
            }
        __syncthreads();
        if (tid < 128)
            g_gpart[((size_t)b*16 + mblk)*512 + c0 + tid] = cs_sm[tid] + cs_sm[128 + tid];
    }
}

// ---------------- aspect (hidden cancels; M collapses to 1) + fused broadcast ----------------
__global__ __launch_bounds__(256) void k_aspect_bcast(const float* __restrict__ Wa,
                                                      const float* __restrict__ Ws,
                                                      float* __restrict__ out){
    __shared__ float g[512];
    __shared__ float cond[512];
    __shared__ float uh[8192];
    __shared__ float b2[256];
    __shared__ float c2[256];
    __shared__ float s2[512];
    __shared__ __align__(16) float v2[512];
    __shared__ float facu[32];
    __shared__ float score[16];
    int b = blockIdx.x, tid = threadIdx.x;
    const float invN = 1.f/1024.f;
    for (int e = tid; e < JUn; e += 256){
        int j = e >> 5, uu = e & 31;
        float t = 0.f;
        #pragma unroll
        for (int mb = 0; mb < 16; mb++) t += g_gpart[((size_t)b*16 + mb)*512 + uu*16 + j];
        g[j*32 + uu] = t*invN;
    }
    __syncthreads();
    if (tid == 0){
        float gw[CNn], mx = -1e30f;
        for (int i = 0; i < CNn; i++){
            float s = 0.f;
            for (int uu = 0; uu < CSn; uu++) s += g[i*32+uu]*Wa[uu];
            gw[i] = s; mx = fmaxf(mx, s);
        }
        float sum = 0.f;
        for (int i = 0; i < CNn; i++){ gw[i] = expf(gw[i]-mx); sum += gw[i]; }
        float inv = 1.f/sum;
        for (int i = 0; i < CNn; i++) score[i] = gw[i]*inv;
    }
    __syncthreads();
    for (int e = tid; e < JUn; e += 256)
        cond[e] = g[e]*score[e>>5];
    { int i = tid >> 4, j = tid & 15; b2[i*16+j] = 0.f; }
    __syncthreads();
    for (int e = tid; e < CNn*NAn*CSn; e += 256){
        int i = e >> 9, j = (e >> 5) & 15, uu = e & 31;
        float s = 0.f;
        const float* wrow = Ws + ((size_t)((i*NAn+j)*CSn+uu))*CSn;
        #pragma unroll
        for (int k = 0; k < CSn; k++) s += wrow[k]*cond[i*32+k];
        uh[e] = s;
    }
    __syncthreads();
    for (int it = 0; it < 3; it++){
        if (tid < CNn){
            int i = tid;
            float mx = -1e30f;
            #pragma unroll
            for (int j = 0; j < NAn; j++) mx = fmaxf(mx, b2[i*16+j]);
            float sum = 0.f, r[NAn];
            #pragma unroll
            for (int j = 0; j < NAn; j++){ r[j] = expf(b2[i*16+j]-mx); sum += r[j]; }
            float inv = 1.f/sum;
            #pragma unroll
            for (int j = 0; j < NAn; j++) c2[i*16+j] = r[j]*inv;
        }
        __syncthreads();
        for (int e = tid; e < NAn*CSn; e += 256){
            int j = e >> 5, uu = e & 31;
            float s = 0.f;
            #pragma unroll
            for (int i = 0; i < CNn; i++) s += c2[i*16+j]*uh[(i*NAn+j)*CSn+uu];
            s2[e] = s;
        }
        __syncthreads();
        if (tid < CSn){
            int uu = tid; float ms = 0.f;
            #pragma unroll
            for (int j = 0; j < NAn; j++) ms += s2[j*32+uu]*s2[j*32+uu];
            facu[uu] = sqrtf(ms)/(1.f+ms);
        }
        __syncthreads();
        for (int e = tid; e < NAn*CSn; e += 256)
            v2[e] = s2[e]*facu[e & 31];
        __syncthreads();
        if (it < 2){
            {
                int i = tid >> 4, j = tid & 15;
                float a = 0.f;
                #pragma unroll
                for (int uu = 0; uu < CSn; uu++) a += uh[(i*NAn+j)*CSn+uu]*v2[j*32+uu];
                b2[i*16+j] += a;
            }
            __syncthreads();
        }
    }
    for (int e = tid; e < NAn*CSn; e += 256)
        g_va[b*NAn*CSn + e] = v2[e];
    // fused broadcast: this block writes its batch's full output (512 rows x 512 f)
    const float4* v24 = (const float4*)v2;
    float4* out4 = (float4*)out + (size_t)b*65536;
    #pragma unroll 8
    for (int r = 0; r < 256; r++){
        int i4 = r*256 + tid;
        out4[i4] = v24[i4 & 127];
    }
}

extern "C" void kernel_launch(void* const* d_in, const int* in_sizes, int n_in,
                              void* d_out, int out_size){
    (void)in_sizes; (void)n_in; (void)out_size;
    const float* ge = (const float*)d_in[0];
    // d_in[1] = hidden: cancels exactly in the softmax over capsules; never read.
    const float* Wp = (const float*)d_in[2];
    const float* bp = (const float*)d_in[3];
    const float* Wg = (const float*)d_in[4];
    const float* Wa = (const float*)d_in[5];
    const float* Ws = (const float*)d_in[6];
    float* out = (float*)d_out;

    static int smem_set = 0;
    if (!smem_set){
        cudaFuncSetAttribute(k_routeT, cudaFuncAttributeMaxDynamicSharedMemorySize, SMEM_BYTES);
        smem_set = 1;
    }

    k_primary<<<dim3(16,2,4), 256>>>(Wg, Wp, ge, bp);
    for (int t = 0; t < 3; t++)
        k_routeT<<<dim3(4,16,4), 256, SMEM_BYTES>>>(t);
    k_aspect_bcast<<<4, 256>>>(Wa, Ws, out);
}

// round 13
// speedup vs baseline: 1.1009x; 1.1009x over previous
#include <cuda_runtime.h>
#include <math.h>

#define Bn 4
#define CNn 16
#define NAn 16
#define CSn 32
#define JUn 512
#define GRIDN 128

// dynamic-smem word offsets for k_fused (total 28160 words = 112640 B)
#define AOFF 0        // sA: [2][2560] u32 (s-GEMM A, double buf); aliased by sag[4096] in epilogue
#define BOFF 5120     // sB: [2][2176] u32 (s-GEMM B / T-phase Ut)
#define COFF 9472     // c_smf[512]
#define FOFF 9984     // fb[512]
#define SCOFF 10496   // scp[1]
#define VOFF 10752    // vt: [128][136] u32 (v tile, tf32)
#define SMEM_WORDS 28160
#define SMEM_BYTES (SMEM_WORDS*4)

// -------- scratch (device globals; no allocations anywhere) --------
__device__ float    g_msqp[Bn*4*16];      // squash-norm partials (b, gl, 16)
__device__ float    g_WgT[128*512];       // fp32 Wg permuted: [ik=k*32+i][col'=u*16+j]
__device__ unsigned g_Ut[Bn*1024*128];    // tf32 UNSCALED U (flat reinterpret view)
__device__ float    g_apart[Bn*8*4*512];  // agreement partials [b][mblk][cblk][i*16+j]
__device__ float    g_blog[Bn*512];       // routing logits
__device__ float    g_gpart[Bn*8*512];    // colsum partials of final v [b][mblk][col']
__device__ float    g_va[Bn*NAn*CSn];     // aspect output
__device__ unsigned g_barcnt[4];          // grid barrier counters (monotonic, epoch-inferred)

// ---------------- helpers ----------------
__device__ __forceinline__ unsigned f2tf(float f){
    unsigned r; asm("cvt.rna.tf32.f32 %0, %1;" : "=r"(r) : "f"(f)); return r;
}
__device__ __forceinline__ void mma_tf32(float* d, unsigned a0, unsigned a1,
                                         unsigned a2, unsigned a3,
                                         unsigned b0, unsigned b1){
    asm volatile(
        "mma.sync.aligned.m16n8k8.row.col.f32.tf32.tf32.f32 "
        "{%0,%1,%2,%3}, {%4,%5,%6,%7}, {%8,%9}, {%0,%1,%2,%3};"
        : "+f"(d[0]), "+f"(d[1]), "+f"(d[2]), "+f"(d[3])
        : "r"(a0), "r"(a1), "r"(a2), "r"(a3), "r"(b0), "r"(b1));
}
__device__ __forceinline__ unsigned s2u(const void* p){
    return (unsigned)__cvta_generic_to_shared(p);
}
__device__ __forceinline__ void cpa16(unsigned d, const void* s){
    asm volatile("cp.async.cg.shared.global [%0], [%1], 16;" :: "r"(d), "l"(s));
}
__device__ __forceinline__ void cpa_commit(){ asm volatile("cp.async.commit_group;"); }
template<int N> __device__ __forceinline__ void cpa_wait(){
    asm volatile("cp.async.wait_group %0;" :: "n"(N));
}
__device__ __forceinline__ void gbar(int p){
    __threadfence();
    __syncthreads();
    if (threadIdx.x == 0){
        unsigned old = atomicAdd(&g_barcnt[p], 1u);
        unsigned target = (old/GRIDN + 1u)*GRIDN;
        while (*((volatile unsigned*)&g_barcnt[p]) < target) __nanosleep(64);
        __threadfence();
    }
    __syncthreads();
}

// ---------------- primary: Wg permute + 64m x 64n GEMM (inline cvt), k=512 ----------------
// grid (16 nblk, 2 mblk, 4 b)
__global__ __launch_bounds__(256) void k_primary(const float* __restrict__ Wg,
                                                 const float* __restrict__ Wp,
                                                 const float* __restrict__ X,
                                                 const float* __restrict__ bp){
    __shared__ __align__(16) unsigned sA[2][1280];  // [64m][20]
    __shared__ __align__(16) unsigned sB[2][1152];  // [16k][72]
    __shared__ float red[8];
    int nblk = blockIdx.x, mblk = blockIdx.y, b = blockIdx.z;
    int n0 = nblk*64, m0 = mblk*64;
    int tid = threadIdx.x, w = tid>>5, lane = tid&31, gid = lane>>2, t4 = lane&3;
    int wm = w>>1, wn = w&1;

    // Wg permute: 512 elems per block (128 blocks cover 65536)
    {
        int lb = blockIdx.x + blockIdx.y*16 + blockIdx.z*32;
        #pragma unroll
        for (int r = 0; r < 2; r++){
            int e = lb*512 + r*256 + tid;
            int ik = e >> 9, col = e & 511;
            int uu = col >> 4, j = col & 15, i = ik & 31, k = ik >> 5;
            g_WgT[e] = Wg[((i*16 + j)*32 + uu)*4 + k];
        }
    }

    const float* Ap = Wp + (size_t)m0*512;
    const float* Bp = X + (size_t)b*524288;
    int arow = tid>>2, aq = tid&3;
    int brow = tid>>4, bq = tid&15;
    float4 ra = *(const float4*)(Ap + (size_t)arow*512 + aq*4);
    float4 rb = *(const float4*)(Bp + (size_t)brow*1024 + n0 + bq*4);
    float d[4][4] = {};
    for (int ch = 0; ch < 32; ch++){
        int buf = ch & 1;
        {
            uint4 oa; oa.x=f2tf(ra.x); oa.y=f2tf(ra.y); oa.z=f2tf(ra.z); oa.w=f2tf(ra.w);
            *(uint4*)&sA[buf][arow*20 + aq*4] = oa;
            uint4 ob; ob.x=f2tf(rb.x); ob.y=f2tf(rb.y); ob.z=f2tf(rb.z); ob.w=f2tf(rb.w);
            *(uint4*)&sB[buf][brow*72 + bq*4] = ob;
        }
        if (ch < 31){
            ra = *(const float4*)(Ap + (size_t)arow*512 + (ch+1)*16 + aq*4);
            rb = *(const float4*)(Bp + (size_t)((ch+1)*16+brow)*1024 + n0 + bq*4);
        }
        __syncthreads();
        #pragma unroll
        for (int ks = 0; ks < 2; ks++){
            int rbse = (wm*16+gid)*20 + ks*8 + t4;
            unsigned a0 = sA[buf][rbse], a1 = sA[buf][rbse+160];
            unsigned a2 = sA[buf][rbse+4], a3 = sA[buf][rbse+164];
            #pragma unroll
            for (int nt = 0; nt < 4; nt++){
                int cb = (ks*8+t4)*72 + wn*32 + nt*8 + gid;
                unsigned b0 = sB[buf][cb], b1 = sB[buf][cb + 288];
                mma_tf32(d[nt], a0, a1, a2, a3, b0, b1);
            }
        }
        __syncthreads();
    }
    float ssq = 0.f;
    unsigned* Ub = g_Ut + (size_t)b*131072;
    int mA = m0 + wm*16 + gid, mB = mA + 8;
    float biasA = bp[mA], biasB = bp[mB];
    #pragma unroll
    for (int nt = 0; nt < 4; nt++){
        int col = n0 + wn*32 + nt*8 + t4*2;
        float v0 = d[nt][0]+biasA, v1 = d[nt][1]+biasA;
        float v2 = d[nt][2]+biasB, v3 = d[nt][3]+biasB;
        uint2 pa; pa.x = f2tf(v0); pa.y = f2tf(v1);
        uint2 pb; pb.x = f2tf(v2); pb.y = f2tf(v3);
        *(uint2*)&Ub[(size_t)mA*1024 + col] = pa;
        *(uint2*)&Ub[(size_t)mB*1024 + col] = pb;
        ssq += v0*v0+v1*v1+v2*v2+v3*v3;
    }
    #pragma unroll
    for (int o = 16; o; o >>= 1) ssq += __shfl_xor_sync(0xffffffffu, ssq, o);
    if (lane == 0) red[w] = ssq;
    __syncthreads();
    if (tid < 2){
        float s = red[tid*4] + red[tid*4+1] + red[tid*4+2] + red[tid*4+3];
        g_msqp[(b*4 + mblk*2 + tid)*16 + nblk] = s;
    }
}

// ---------------- routeT phase body (R11-proven): 128m x 128col' + in-block T + agreement ----------------
__device__ __forceinline__ void routeT_body(int t, int cblk, int mblk, int b, float* sp){
    unsigned* sA = (unsigned*)sp + AOFF;
    unsigned* sB = (unsigned*)sp + BOFF;
    float* c_smf = sp + COFF;
    float* fb    = sp + FOFF;
    float* scp1  = sp + SCOFF;
    unsigned* vt = (unsigned*)sp + VOFF;
    int m0 = mblk*128, c0 = cblk*128;
    int tid = threadIdx.x, w = tid>>5, lane = tid&31, gid = lane>>2, t4 = lane&3;
    int wm = w>>2, wn = w&3;

    if (tid == 0){
        int grp = mblk >> 1;
        float s = 0.f;
        #pragma unroll
        for (int p = 0; p < 16; p++) s += g_msqp[(b*4+grp)*16 + p];
        scp1[0] = sqrtf(s)/(1.f+s);
    }
    if (t >= 1){
        #pragma unroll
        for (int r = 0; r < 2; r++){
            int e = r*256 + tid;
            float s = (t == 2) ? g_blog[b*512 + e] : 0.f;
            const float* ap = g_apart + (size_t)b*16384 + e;
            #pragma unroll
            for (int p = 0; p < 32; p++) s += ap[p*512];
            fb[e] = s;
        }
    } else {
        c_smf[tid] = 0.0625f; c_smf[tid+256] = 0.0625f;
    }
    __syncthreads();
    if (t == 1 && mblk == 0 && cblk == 0)
        for (int e = tid; e < 512; e += 256) g_blog[b*512 + e] = fb[e];
    if (t >= 1 && tid < 32){
        int i = tid;
        float row[CNn], mx = -1e30f;
        #pragma unroll
        for (int j = 0; j < CNn; j++){ row[j] = fb[i*16 + j]; mx = fmaxf(mx, row[j]); }
        float sum = 0.f;
        #pragma unroll
        for (int j = 0; j < CNn; j++){ row[j] = expf(row[j]-mx); sum += row[j]; }
        float inv = 1.f/sum;
        #pragma unroll
        for (int j = 0; j < CNn; j++) c_smf[i*16 + j] = row[j]*inv;
    }
    __syncthreads();
    float sc = scp1[0];

    const unsigned* Ag = g_Ut + (size_t)b*131072 + (size_t)m0*128;
    int brow = tid >> 4;
    int bcol4 = (tid & 15)*2;
    const float4* c4p0 = (const float4*)&c_smf[0];

#define RT_STAGE_A(ch, bf) { \
    { int f=tid;     int row=f>>2,q=f&3; cpa16(s2u(&sA[(bf)*2560+row*20+q*4]), Ag + row*128 + (ch)*16 + q*4); } \
    { int f=tid+256; int row=f>>2,q=f&3; cpa16(s2u(&sA[(bf)*2560+row*20+q*4]), Ag + row*128 + (ch)*16 + q*4); } \
    cpa_commit(); }

    float4 curB0, curB1;
    {
        const float4* src = (const float4*)(g_WgT + (size_t)brow*512 + c0) + bcol4;
        curB0 = src[0]; curB1 = src[1];
    }
    RT_STAGE_A(0, 0);
    float d[4][4][4] = {};
    for (int ch = 0; ch < 8; ch++){
        int buf = ch & 1;
        if (ch < 7) RT_STAGE_A(ch+1, buf^1);
        {
            int i = ((ch & 1)*16 + brow);
            float4 cv0 = c4p0[i*4 + (bcol4 & 3)];
            float4 cv1 = c4p0[i*4 + ((bcol4+1) & 3)];
            uint4 o0, o1;
            o0.x=f2tf(curB0.x*cv0.x); o0.y=f2tf(curB0.y*cv0.y);
            o0.z=f2tf(curB0.z*cv0.z); o0.w=f2tf(curB0.w*cv0.w);
            o1.x=f2tf(curB1.x*cv1.x); o1.y=f2tf(curB1.y*cv1.y);
            o1.z=f2tf(curB1.z*cv1.z); o1.w=f2tf(curB1.w*cv1.w);
            uint4* dst = (uint4*)&sB[buf*2176 + brow*136 + bcol4*4];
            dst[0] = o0; dst[1] = o1;
        }
        if (ch < 7){
            const float4* src = (const float4*)(g_WgT + (size_t)((ch+1)*16+brow)*512 + c0) + bcol4;
            curB0 = src[0]; curB1 = src[1];
        }
        if (ch < 7) cpa_wait<1>(); else cpa_wait<0>();
        __syncthreads();
        #pragma unroll
        for (int ks = 0; ks < 2; ks++){
            unsigned a[4][4];
            #pragma unroll
            for (int mt = 0; mt < 4; mt++){
                int rb = buf*2560 + (wm*64 + mt*16 + gid)*20 + ks*8 + t4;
                a[mt][0]=sA[rb]; a[mt][1]=sA[rb+160];
                a[mt][2]=sA[rb+4]; a[mt][3]=sA[rb+164];
            }
            #pragma unroll
            for (int nt = 0; nt < 4; nt++){
                int cb = buf*2176 + (ks*8+t4)*136 + wn*32 + nt*8 + gid;
                unsigned b0 = sB[cb], b1 = sB[cb + 544];
                #pragma unroll
                for (int mt = 0; mt < 4; mt++)
                    mma_tf32(d[mt][nt], a[mt][0],a[mt][1],a[mt][2],a[mt][3], b0, b1);
            }
        }
        __syncthreads();
    }

    // squash over j (sc applied here; Ut unscaled)
    #pragma unroll
    for (int mt = 0; mt < 4; mt++){
        #pragma unroll
        for (int off = 0; off < 2; off++){
            float p0 = d[mt][0][off*2]*d[mt][0][off*2] + d[mt][0][off*2+1]*d[mt][0][off*2+1]
                     + d[mt][1][off*2]*d[mt][1][off*2] + d[mt][1][off*2+1]*d[mt][1][off*2+1];
            float p1 = d[mt][2][off*2]*d[mt][2][off*2] + d[mt][2][off*2+1]*d[mt][2][off*2+1]
                     + d[mt][3][off*2]*d[mt][3][off*2] + d[mt][3][off*2+1]*d[mt][3][off*2+1];
            p0 += __shfl_xor_sync(0xffffffffu, p0, 1); p0 += __shfl_xor_sync(0xffffffffu, p0, 2);
            p1 += __shfl_xor_sync(0xffffffffu, p1, 1); p1 += __shfl_xor_sync(0xffffffffu, p1, 2);
            float q0 = sc*sc*p0, q1 = sc*sc*p1;
            float f0 = sc*sqrtf(q0)/(1.f + q0), f1 = sc*sqrtf(q1)/(1.f + q1);
            d[mt][0][off*2] *= f0; d[mt][0][off*2+1] *= f0;
            d[mt][1][off*2] *= f0; d[mt][1][off*2+1] *= f0;
            d[mt][2][off*2] *= f1; d[mt][2][off*2+1] *= f1;
            d[mt][3][off*2] *= f1; d[mt][3][off*2+1] *= f1;
        }
    }
    if (t < 2){
        #pragma unroll
        for (int mt = 0; mt < 4; mt++)
            #pragma unroll
            for (int off = 0; off < 2; off++){
                int m = wm*64 + mt*16 + gid + off*8;
                #pragma unroll
                for (int nt = 0; nt < 4; nt++){
                    int col = wn*32 + nt*8 + t4*2;
                    vt[m*136 + col]     = f2tf(d[mt][nt][off*2]);
                    vt[m*136 + col + 1] = f2tf(d[mt][nt][off*2+1]);
                }
            }
        __syncthreads();
        int wik = w >> 1, wju = w & 1;
        float d2[2][8][4] = {};
#define T_STAGE(ch, bf) { \
    { int f=tid;     int row=f>>5,q=f&31; cpa16(s2u(&sB[(bf)*2176+row*136+q*4]), Ag + (size_t)((ch)*16+row)*128 + q*4); } \
    { int f=tid+256; int row=f>>5,q=f&31; cpa16(s2u(&sB[(bf)*2176+row*136+q*4]), Ag + (size_t)((ch)*16+row)*128 + q*4); } \
    cpa_commit(); }
        T_STAGE(0, 0);
        for (int ch = 0; ch < 8; ch++){
            int buf = ch & 1;
            if (ch < 7){ T_STAGE(ch+1, buf^1); cpa_wait<1>(); } else cpa_wait<0>();
            __syncthreads();
            #pragma unroll
            for (int ks = 0; ks < 2; ks++){
                unsigned a[2][4];
                #pragma unroll
                for (int mt = 0; mt < 2; mt++){
                    int ikb = wik*32 + mt*16 + gid;
                    a[mt][0] = sB[buf*2176 + (ks*8+t4)*136 + ikb];
                    a[mt][1] = sB[buf*2176 + (ks*8+t4)*136 + ikb + 8];
                    a[mt][2] = sB[buf*2176 + (ks*8+t4+4)*136 + ikb];
                    a[mt][3] = sB[buf*2176 + (ks*8+t4+4)*136 + ikb + 8];
                }
                #pragma unroll
                for (int nt = 0; nt < 8; nt++){
                    int cb = wju*64 + nt*8 + gid;
                    unsigned b0 = vt[(ch*16 + ks*8+t4)*136 + cb];
                    unsigned b1 = vt[(ch*16 + ks*8+t4+4)*136 + cb];
                    mma_tf32(d2[0][nt], a[0][0],a[0][1],a[0][2],a[0][3], b0, b1);
                    mma_tf32(d2[1][nt], a[1][0],a[1][1],a[1][2],a[1][3], b0, b1);
                }
            }
            __syncthreads();
        }
        float p[4][4] = {};
        #pragma unroll
        for (int mt = 0; mt < 2; mt++)
            #pragma unroll
            for (int off = 0; off < 2; off++){
                int r = wik*32 + mt*16 + off*8 + gid;
                #pragma unroll
                for (int nt = 0; nt < 8; nt++){
                    int col = c0 + wju*64 + nt*8 + t4*2;
                    float2 wv = *(const float2*)&g_WgT[(size_t)r*512 + col];
                    int pi = mt*2 + off, js = (nt & 1)*2;
                    p[pi][js]   += d2[mt][nt][off*2]   * wv.x;
                    p[pi][js+1] += d2[mt][nt][off*2+1] * wv.y;
                }
            }
        float* sag = sp + AOFF;
        #pragma unroll
        for (int pi = 0; pi < 4; pi++)
            #pragma unroll
            for (int js = 0; js < 4; js++)
                sag[(w*32 + lane)*16 + pi*4 + js] = p[pi][js];
        __syncthreads();
        float wsc = sc*(1.f/1024.f);
        #pragma unroll
        for (int it = 0; it < 2; it++){
            int idx = it*256 + tid;
            int i = idx >> 4, j = idx & 15;
            int lgid = i & 7, pi = ((i>>4)<<1) | ((i>>3)&1);
            int lt4 = (j & 7) >> 1, js = ((j>>3)<<1) | (j&1);
            int ln = lgid*4 + lt4;
            float s = 0.f;
            #pragma unroll
            for (int ww = 0; ww < 8; ww++) s += sag[(ww*32 + ln)*16 + pi*4 + js];
            g_apart[(((size_t)b*8 + mblk)*4 + cblk)*512 + idx] = s*wsc;
        }
    } else {
        float* cs_sm = c_smf;
        #pragma unroll
        for (int nt = 0; nt < 4; nt++)
            #pragma unroll
            for (int c = 0; c < 2; c++){
                float s = 0.f;
                #pragma unroll
                for (int mt = 0; mt < 4; mt++) s += d[mt][nt][c] + d[mt][nt][2+c];
                s += __shfl_xor_sync(0xffffffffu, s, 4);
                s += __shfl_xor_sync(0xffffffffu, s, 8);
                s += __shfl_xor_sync(0xffffffffu, s, 16);
                if (gid == 0) cs_sm[wm*128 + wn*32 + nt*8 + t4*2 + c] = s;
            }
        __syncthreads();
        if (tid < 128)
            g_gpart[((size_t)b*8 + mblk)*512 + c0 + tid] = cs_sm[tid] + cs_sm[128 + tid];
    }
}

// ---------------- aspect phase (hidden cancels; M collapses to 1) ----------------
__device__ __forceinline__ void aspect_body(int b, const float* __restrict__ Wa,
                                            const float* __restrict__ Ws, float* sp){
    float* g    = sp;
    float* cond = sp + 512;
    float* uh   = sp + 1024;     // [8192]
    float* b2   = sp + 9216;
    float* c2   = sp + 9472;
    float* s2   = sp + 9728;
    float* v2   = sp + 10240;
    float* facu = sp + 10752;
    float* score= sp + 10784;
    int tid = threadIdx.x;
    __syncthreads();
    const float invN = 1.f/1024.f;
    for (int e = tid; e < JUn; e += 256){
        int j = e >> 5, uu = e & 31;
        float t = 0.f;
        #pragma unroll
        for (int mb = 0; mb < 8; mb++) t += g_gpart[((size_t)b*8 + mb)*512 + uu*16 + j];
        g[j*32 + uu] = t*invN;
    }
    __syncthreads();
    if (tid == 0){
        float gw[CNn], mx = -1e30f;
        for (int i = 0; i < CNn; i++){
            float s = 0.f;
            for (int uu = 0; uu < CSn; uu++) s += g[i*32+uu]*Wa[uu];
            gw[i] = s; mx = fmaxf(mx, s);
        }
        float sum = 0.f;
        for (int i = 0; i < CNn; i++){ gw[i] = expf(gw[i]-mx); sum += gw[i]; }
        float inv = 1.f/sum;
        for (int i = 0; i < CNn; i++) score[i] = gw[i]*inv;
    }
    __syncthreads();
    for (int e = tid; e < JUn; e += 256)
        cond[e] = g[e]*score[e>>5];
    { int i = tid >> 4, j = tid & 15; b2[i*16+j] = 0.f; }
    __syncthreads();
    for (int e = tid; e < CNn*NAn*CSn; e += 256){
        int i = e >> 9, j = (e >> 5) & 15, uu = e & 31;
        float s = 0.f;
        const float* wrow = Ws + ((size_t)((i*NAn+j)*CSn+uu))*CSn;
        #pragma unroll
        for (int k = 0; k < CSn; k++) s += wrow[k]*cond[i*32+k];
        uh[e] = s;
    }
    __syncthreads();
    for (int it = 0; it < 3; it++){
        if (tid < CNn){
            int i = tid;
            float mx = -1e30f;
            #pragma unroll
            for (int j = 0; j < NAn; j++) mx = fmaxf(mx, b2[i*16+j]);
            float sum = 0.f, r[NAn];
            #pragma unroll
            for (int j = 0; j < NAn; j++){ r[j] = expf(b2[i*16+j]-mx); sum += r[j]; }
            float inv = 1.f/sum;
            #pragma unroll
            for (int j = 0; j < NAn; j++) c2[i*16+j] = r[j]*inv;
        }
        __syncthreads();
        for (int e = tid; e < NAn*CSn; e += 256){
            int j = e >> 5, uu = e & 31;
            float s = 0.f;
            #pragma unroll
            for (int i = 0; i < CNn; i++) s += c2[i*16+j]*uh[(i*NAn+j)*CSn+uu];
            s2[e] = s;
        }
        __syncthreads();
        if (tid < CSn){
            int uu = tid; float ms = 0.f;
            #pragma unroll
            for (int j = 0; j < NAn; j++) ms += s2[j*32+uu]*s2[j*32+uu];
            facu[uu] = sqrtf(ms)/(1.f+ms);
        }
        __syncthreads();
        for (int e = tid; e < NAn*CSn; e += 256)
            v2[e] = s2[e]*facu[e & 31];
        __syncthreads();
        if (it < 2){
            {
                int i = tid >> 4, j = tid & 15;
                float a = 0.f;
                #pragma unroll
                for (int uu = 0; uu < CSn; uu++) a += uh[(i*NAn+j)*CSn+uu]*v2[j*32+uu];
                b2[i*16+j] += a;
            }
            __syncthreads();
        }
    }
    for (int e = tid; e < NAn*CSn; e += 256)
        g_va[b*NAn*CSn + e] = v2[e];
}

// ---------------- fused persistent kernel: routing x3 + aspect + broadcast ----------------
__global__ void k_fused(const float* __restrict__ Wa, const float* __restrict__ Ws,
                        float* __restrict__ out){
    extern __shared__ __align__(16) float sp[];
    int bid = blockIdx.x;
    int cblk = bid & 3, mblk = (bid >> 2) & 7, b = bid >> 5;

    routeT_body(0, cblk, mblk, b, sp);
    gbar(0);
    routeT_body(1, cblk, mblk, b, sp);
    gbar(1);
    routeT_body(2, cblk, mblk, b, sp);
    gbar(2);
    if (bid < Bn) aspect_body(bid, Wa, Ws, sp);
    gbar(3);
    // broadcast: 128 blocks x 256 threads x 8 float4 = 262144 float4
    const float4* va4 = (const float4*)g_va;
    float4* out4 = (float4*)out;
    int tid = threadIdx.x;
    #pragma unroll
    for (int r = 0; r < 8; r++){
        int i4 = bid*2048 + r*256 + tid;
        int bb = i4 >> 16;
        out4[i4] = va4[(bb << 7) + (i4 & 127)];
    }
}

extern "C" void kernel_launch(void* const* d_in, const int* in_sizes, int n_in,
                              void* d_out, int out_size){
    (void)in_sizes; (void)n_in; (void)out_size;
    const float* ge = (const float*)d_in[0];
    // d_in[1] = hidden: cancels exactly in the softmax over capsules; never read.
    const float* Wp = (const float*)d_in[2];
    const float* bp = (const float*)d_in[3];
    const float* Wg = (const float*)d_in[4];
    const float* Wa = (const float*)d_in[5];
    const float* Ws = (const float*)d_in[6];
    float* out = (float*)d_out;

    static int smem_set = 0;
    if (!smem_set){
        cudaFuncSetAttribute(k_fused, cudaFuncAttributeMaxDynamicSharedMemorySize, SMEM_BYTES);
        smem_set = 1;
    }

    k_primary<<<dim3(16,2,4), 256>>>(Wg, Wp, ge, bp);
    k_fused<<<GRIDN, 256, SMEM_BYTES>>>(Wa, Ws, out);
}